// round 15
// baseline (speedup 1.0000x reference)
#include <cuda_runtime.h>
#include <cuda_fp16.h>
#include <stdint.h>
#include <stddef.h>

#define B_DIM 8192
#define N_DIM 2048   // GEMM K (rows of weight)
#define M_DIM 2048   // cols of weight

// ---------------- device scratch (no allocation allowed) -------------------
__device__ __align__(16) __half g_Xhi[(size_t)B_DIM * N_DIM];
__device__ __align__(16) __half g_Xlo[(size_t)B_DIM * N_DIM];
__device__ __align__(16) __half g_Whit[(size_t)M_DIM * N_DIM]; // new_weight^T hi: [j][i]
__device__ __align__(16) __half g_Wlot[(size_t)M_DIM * N_DIM]; // new_weight^T lo
__device__ float g_rowsum[N_DIM];
__device__ float g_colpart[64 * M_DIM];

// ---------------- PTX helpers (baseline PTX only, no 'a' features) ---------
__device__ __forceinline__ uint32_t smem_u32(const void* p) {
    uint32_t a;
    asm("{ .reg .u64 t; cvta.to.shared.u64 t, %1; cvt.u32.u64 %0, t; }"
        : "=r"(a) : "l"(p));
    return a;
}
__device__ __forceinline__ void cp16(uint32_t dst, const void* src) {
    unsigned long long g = (unsigned long long)__cvta_generic_to_global(src);
    asm volatile("cp.async.cg.shared.global [%0], [%1], 16;"
                 :: "r"(dst), "l"(g) : "memory");
}
__device__ __forceinline__ void cp_commit() {
    asm volatile("cp.async.commit_group;" ::: "memory");
}
__device__ __forceinline__ void ldsm_x4(uint32_t& r0, uint32_t& r1,
                                        uint32_t& r2, uint32_t& r3, uint32_t addr) {
    asm volatile("ldmatrix.sync.aligned.m8n8.x4.shared.b16 {%0,%1,%2,%3}, [%4];"
                 : "=r"(r0), "=r"(r1), "=r"(r2), "=r"(r3) : "r"(addr));
}
__device__ __forceinline__ void mma16816(float& c0, float& c1, float& c2, float& c3,
                                         uint32_t a0, uint32_t a1, uint32_t a2, uint32_t a3,
                                         uint32_t b0, uint32_t b1) {
    asm volatile(
        "mma.sync.aligned.m16n8k16.row.col.f32.f16.f16.f32 "
        "{%0,%1,%2,%3}, {%4,%5,%6,%7}, {%8,%9}, {%0,%1,%2,%3};"
        : "+f"(c0), "+f"(c1), "+f"(c2), "+f"(c3)
        : "r"(a0), "r"(a1), "r"(a2), "r"(a3), "r"(b0), "r"(b1));
}

// ---------------- reductions -------------------------------------------------
__device__ __forceinline__ float block_reduce_sum256(float v) {
    __shared__ float s[8];
#pragma unroll
    for (int o = 16; o; o >>= 1) v += __shfl_xor_sync(0xffffffffu, v, o);
    if ((threadIdx.x & 31) == 0) s[threadIdx.x >> 5] = v;
    __syncthreads();
    if (threadIdx.x < 32) {
        float t = (threadIdx.x < 8) ? s[threadIdx.x] : 0.0f;
#pragma unroll
        for (int o = 4; o; o >>= 1) t += __shfl_xor_sync(0xffffffffu, t, o);
        if (threadIdx.x == 0) s[0] = t;
    }
    __syncthreads();
    float r = s[0];
    __syncthreads();
    return r;
}
__device__ __forceinline__ float block_reduce_max256(float v) {
    __shared__ float s[8];
#pragma unroll
    for (int o = 16; o; o >>= 1) v = fmaxf(v, __shfl_xor_sync(0xffffffffu, v, o));
    if ((threadIdx.x & 31) == 0) s[threadIdx.x >> 5] = v;
    __syncthreads();
    if (threadIdx.x < 32) {
        float t = (threadIdx.x < 8) ? s[threadIdx.x] : -3.402823466e38f;
#pragma unroll
        for (int o = 4; o; o >>= 1) t = fmaxf(t, __shfl_xor_sync(0xffffffffu, t, o));
        if (threadIdx.x == 0) s[0] = t;
    }
    __syncthreads();
    float r = s[0];
    __syncthreads();
    return r;
}

// ---------------- fused prep: split X || single-pass W stats ----------------
// blocks [0,8192): split X into hi/lo fp16
// blocks [8192,8256): 32 rows each -> column partials AND complete row sums
__global__ void __launch_bounds__(256) prep_kernel(const float* __restrict__ X,
                                                   const float* __restrict__ W) {
    int bid = blockIdx.x;
    if (bid < 8192) {
        size_t idx = (size_t)bid * 256 + threadIdx.x; // one idx = 8 elems
        const float4* x4 = (const float4*)X;
        float4 a = x4[idx * 2 + 0];
        float4 b = x4[idx * 2 + 1];
        float v[8] = {a.x, a.y, a.z, a.w, b.x, b.y, b.z, b.w};
        union U { __half h[8]; uint4 u; } uh, ul;
#pragma unroll
        for (int i = 0; i < 8; i++) {
            __half hi = __float2half_rn(v[i]);
            uh.h[i] = hi;
            ul.h[i] = __float2half_rn(v[i] - __half2float(hi));
        }
        ((uint4*)g_Xhi)[idx] = uh.u;
        ((uint4*)g_Xlo)[idx] = ul.u;
    } else {
        __shared__ float sRowP[32][8];
        int pb = bid - 8192;
        int t = threadIdx.x, lane = t & 31, wid = t >> 5;
        float acc[8] = {0, 0, 0, 0, 0, 0, 0, 0};
        int r0 = pb * 32;
        for (int i = 0; i < 32; i++) {
            const float* row = W + (size_t)(r0 + i) * M_DIM;
            float rp = 0.0f;
#pragma unroll
            for (int u = 0; u < 8; u++) {
                float v = row[u * 256 + t];
                acc[u] += v;
                rp += v;
            }
#pragma unroll
            for (int o = 16; o; o >>= 1) rp += __shfl_xor_sync(0xffffffffu, rp, o);
            if (lane == 0) sRowP[i][wid] = rp;
        }
#pragma unroll
        for (int u = 0; u < 8; u++)
            g_colpart[pb * M_DIM + u * 256 + t] = acc[u];
        __syncthreads();
        if (t < 32) {
            float s = 0.0f;
#pragma unroll
            for (int w = 0; w < 8; w++) s += sRowP[t][w];
            g_rowsum[r0 + t] = s;
        }
    }
}

// per-cell MLP -> new_weight (hi/lo fp16), stored TRANSPOSED ([j][i], K-major B)
// col sums reduced in-block from g_colpart; 4 cells/thread processed together.
__global__ void __launch_bounds__(256) mlp_kernel(
    const float* __restrict__ W,
    const float* __restrict__ W1, const float* __restrict__ b1,
    const float* __restrict__ W2, const float* __restrict__ b2,
    const float* __restrict__ W3, const float* __restrict__ b3) {
    __shared__ float sW1[30], sb1[10], sW2[100], sb2[10], sW3[10], sb3v[1];
    __shared__ float sColP[8][32], sCol[32];
    __shared__ __half shi[32][33], slo[32][33];
    int t = threadIdx.x;
    int tj = t & 31, ti = t >> 5;
    int i0 = blockIdx.y * 32, j0 = blockIdx.x * 32;
    if (t < 30) sW1[t] = W1[t];
    if (t < 10) { sb1[t] = b1[t]; sb2[t] = b2[t]; sW3[t] = W3[t]; }
    if (t >= 32 && t < 132) sW2[t - 32] = W2[t - 32];
    if (t == 0) sb3v[0] = b3[0];
    {
        float p = 0.0f;
#pragma unroll
        for (int b = 0; b < 8; b++) p += g_colpart[(ti + 8 * b) * M_DIM + j0 + tj];
        sColP[ti][tj] = p;
    }
    __syncthreads();
    if (t < 32) {
        float s = 0.0f;
#pragma unroll
        for (int b = 0; b < 8; b++) s += sColP[b][t];
        sCol[t] = s;
    }
    __syncthreads();

    float w[4], f1[4], f2[4], h1[4][10];
#pragma unroll
    for (int rr = 0; rr < 4; rr++) {
        int il = ti + 8 * rr;
        int i = i0 + il, j = j0 + tj;
        w[rr] = W[(size_t)i * M_DIM + j];
        f1[rr] = (sCol[tj] - w[rr]) * (1.0f / 2047.0f);     // fwd (LOO col mean)
        f2[rr] = (g_rowsum[i] - w[rr]) * (1.0f / 2047.0f);  // bwd (LOO row mean)
    }
#pragma unroll
    for (int k = 0; k < 10; k++) {
        float wa = sW1[k], wb = sW1[10 + k], wc = sW1[20 + k], bb = sb1[k];
#pragma unroll
        for (int rr = 0; rr < 4; rr++)
            h1[rr][k] = fmaxf(0.f, w[rr] * wa + f1[rr] * wb + f2[rr] * wc + bb);
    }
    float u[4];
#pragma unroll
    for (int rr = 0; rr < 4; rr++) u[rr] = sb3v[0];
#pragma unroll
    for (int k = 0; k < 10; k++) {
        float a0 = sb2[k], a1v = sb2[k], a2 = sb2[k], a3 = sb2[k];
#pragma unroll
        for (int l = 0; l < 10; l++) {
            float wkl = sW2[l * 10 + k];
            a0 += h1[0][l] * wkl;
            a1v += h1[1][l] * wkl;
            a2 += h1[2][l] * wkl;
            a3 += h1[3][l] * wkl;
        }
        float w3k = sW3[k];
        u[0] += fmaxf(0.f, a0) * w3k;
        u[1] += fmaxf(0.f, a1v) * w3k;
        u[2] += fmaxf(0.f, a2) * w3k;
        u[3] += fmaxf(0.f, a3) * w3k;
    }
#pragma unroll
    for (int rr = 0; rr < 4; rr++) {
        int il = ti + 8 * rr;
        float nw = w[rr] + u[rr];
        __half hi = __float2half_rn(nw);
        shi[il][tj] = hi;
        slo[il][tj] = __float2half_rn(nw - __half2float(hi));
    }
    __syncthreads();
#pragma unroll
    for (int rr = 0; rr < 4; rr++) {
        int jl = ti + 8 * rr, il = tj;
        size_t off = (size_t)(j0 + jl) * N_DIM + i0 + il;
        g_Whit[off] = shi[il][jl];
        g_Wlot[off] = slo[il][jl];
    }
}

// ---------------- GEMM: Y = X @ Wnew via fused fp16x3 split (R10 proven) ----
#define KSTAGE 64
#define PITCHB 144                  // 64 halves (128B) + 16B pad
#define OPB (128 * PITCHB)          // 18432 per operand per stage
#define STGBYTES (4 * OPB)          // 73728 per stage
#define NST 3
#define SMEM_BYTES (NST * STGBYTES) // 221184
#define NSTAGES_TOT 32              // 2048 / 64

__device__ __forceinline__ uint32_t stage_base(int s, uint32_t sb) {
    return sb + (s % NST) * STGBYTES;
}

// one quarter (4 cp16/thread) of a stage's loads; NO commit
__device__ __forceinline__ void load_quarter(int s, int q, int t, int m0, int n0,
                                             uint32_t sb) {
    int kk = s * KSTAGE;
    uint32_t base = stage_base(s, sb);
    int idx = t + q * 256;
    int row = idx >> 3, kc = idx & 7;
    uint32_t so = row * PITCHB + kc * 16;
    size_t goA = (size_t)(m0 + row) * N_DIM + kk + kc * 8;
    size_t goB = (size_t)(n0 + row) * N_DIM + kk + kc * 8;
    cp16(base + 0 * OPB + so, g_Xhi + goA);
    cp16(base + 1 * OPB + so, g_Xlo + goA);
    cp16(base + 2 * OPB + so, g_Whit + goB);
    cp16(base + 3 * OPB + so, g_Wlot + goB);
}

__device__ __forceinline__ void load_stage(int s, int t, int m0, int n0, uint32_t sb) {
#pragma unroll
    for (int q = 0; q < 4; q++) load_quarter(s, q, t, m0, n0, sb);
    cp_commit();
}

#define LOAD_FRAGS(buf, bs, kofs) do {                                             \
    _Pragma("unroll")                                                              \
    for (int mi_ = 0; mi_ < 4; mi_++) {                                            \
        uint32_t ar_ = (a_row + mi_ * 16) * PITCHB + a_koff + (kofs);              \
        ldsm_x4(ahi[buf][mi_][0], ahi[buf][mi_][1], ahi[buf][mi_][2],              \
                ahi[buf][mi_][3], (bs) + 0 * OPB + ar_);                           \
        ldsm_x4(alo[buf][mi_][0], alo[buf][mi_][1], alo[buf][mi_][2],              \
                alo[buf][mi_][3], (bs) + 1 * OPB + ar_);                           \
    }                                                                              \
    _Pragma("unroll")                                                              \
    for (int bi_ = 0; bi_ < 2; bi_++) {                                            \
        uint32_t br_ = (b_row + bi_ * 16) * PITCHB + b_koff + (kofs);              \
        ldsm_x4(bhi[buf][2 * bi_][0], bhi[buf][2 * bi_][1],                        \
                bhi[buf][2 * bi_ + 1][0], bhi[buf][2 * bi_ + 1][1],                \
                (bs) + 2 * OPB + br_);                                             \
        ldsm_x4(blo[buf][2 * bi_][0], blo[buf][2 * bi_][1],                        \
                blo[buf][2 * bi_ + 1][0], blo[buf][2 * bi_ + 1][1],                \
                (bs) + 3 * OPB + br_);                                             \
    }                                                                              \
} while (0)

#define DO_MMAS(buf) do {                                                          \
    _Pragma("unroll")                                                              \
    for (int mi = 0; mi < 4; mi++)                                                 \
        _Pragma("unroll")                                                          \
        for (int ni = 0; ni < 4; ni++)                                             \
            mma16816(acc[mi][ni][0], acc[mi][ni][1], acc[mi][ni][2], acc[mi][ni][3], \
                     ahi[buf][mi][0], ahi[buf][mi][1], ahi[buf][mi][2], ahi[buf][mi][3], \
                     bhi[buf][ni][0], bhi[buf][ni][1]);                            \
    _Pragma("unroll")                                                              \
    for (int mi = 0; mi < 4; mi++)                                                 \
        _Pragma("unroll")                                                          \
        for (int ni = 0; ni < 4; ni++)                                             \
            mma16816(acc[mi][ni][0], acc[mi][ni][1], acc[mi][ni][2], acc[mi][ni][3], \
                     ahi[buf][mi][0], ahi[buf][mi][1], ahi[buf][mi][2], ahi[buf][mi][3], \
                     blo[buf][ni][0], blo[buf][ni][1]);                            \
    _Pragma("unroll")                                                              \
    for (int mi = 0; mi < 4; mi++)                                                 \
        _Pragma("unroll")                                                          \
        for (int ni = 0; ni < 4; ni++)                                             \
            mma16816(acc[mi][ni][0], acc[mi][ni][1], acc[mi][ni][2], acc[mi][ni][3], \
                     alo[buf][mi][0], alo[buf][mi][1], alo[buf][mi][2], alo[buf][mi][3], \
                     bhi[buf][ni][0], bhi[buf][ni][1]);                            \
} while (0)

__global__ void __launch_bounds__(256, 1) gemm_kernel(float* __restrict__ Y) {
    extern __shared__ char smem[];
    uint32_t sb = smem_u32(smem);
    int t = threadIdx.x;
    int lane = t & 31, wid = t >> 5;
    int wm = wid >> 2, wn = wid & 3;             // warp tile origin: (wm*64, wn*32)
    int n0 = blockIdx.x * 128, m0 = blockIdx.y * 128;

    float acc[4][4][4];
#pragma unroll
    for (int i = 0; i < 4; i++)
#pragma unroll
        for (int j = 0; j < 4; j++)
#pragma unroll
            for (int k = 0; k < 4; k++) acc[i][j][k] = 0.0f;

    load_stage(0, t, m0, n0, sb);
    load_stage(1, t, m0, n0, sb);

    uint32_t a_row = wm * 64 + (lane & 15);
    uint32_t a_koff = (lane >> 4) << 4;
    uint32_t b_row = wn * 32 + ((lane >> 3) >> 1) * 8 + (lane & 7);
    uint32_t b_koff = ((lane >> 3) & 1) << 4;

    uint32_t ahi[2][4][4], alo[2][4][4], bhi[2][4][2], blo[2][4][2];

    asm volatile("cp.async.wait_group 1;" ::: "memory"); // stage 0 resident
    __syncthreads();
    LOAD_FRAGS(0, sb, 0);

    int cur = 0;
#pragma unroll 1
    for (int s = 0; s < NSTAGES_TOT; s++) {
        uint32_t bs = stage_base(s, sb);
        uint32_t bsn = stage_base(s + 1, sb);
#pragma unroll
        for (int ks = 0; ks < 3; ks++) {
            if (s + 2 < NSTAGES_TOT) load_quarter(s + 2, ks, t, m0, n0, sb);
            int nxt = cur ^ 1;
            LOAD_FRAGS(nxt, bs, (ks + 1) * 32);
            DO_MMAS(cur);
            cur = nxt;
        }
        if (s + 2 < NSTAGES_TOT) load_quarter(s + 2, 3, t, m0, n0, sb);
        cp_commit();
        asm volatile("cp.async.wait_group 1;" ::: "memory");
        __syncthreads();
        {
            int nxt = cur ^ 1;
            if (s + 1 < NSTAGES_TOT) LOAD_FRAGS(nxt, bsn, 0);
            DO_MMAS(cur);
            cur = nxt;
        }
    }

    int r_base = m0 + wm * 64 + (lane >> 2);
    int c_base = n0 + wn * 32 + 2 * (lane & 3);
#pragma unroll
    for (int mi = 0; mi < 4; mi++)
#pragma unroll
        for (int ni = 0; ni < 4; ni++) {
            size_t off0 = (size_t)(r_base + mi * 16) * M_DIM + c_base + ni * 8;
            *(float2*)(Y + off0) = make_float2(acc[mi][ni][0], acc[mi][ni][1]);
            *(float2*)(Y + off0 + 8 * M_DIM) = make_float2(acc[mi][ni][2], acc[mi][ni][3]);
        }
}

// ---------------- softmax (in-place on Y rows) -------------------------------
__global__ void __launch_bounds__(256) softmax_kernel(float* __restrict__ Y) {
    float4* r4 = (float4*)(Y + (size_t)blockIdx.x * M_DIM);
    int t = threadIdx.x;
    float4 a = r4[t], b = r4[t + 256];
    float m = fmaxf(fmaxf(fmaxf(a.x, a.y), fmaxf(a.z, a.w)),
                    fmaxf(fmaxf(b.x, b.y), fmaxf(b.z, b.w)));
    m = block_reduce_max256(m);
    float e0 = __expf(a.x - m), e1 = __expf(a.y - m), e2 = __expf(a.z - m), e3 = __expf(a.w - m);
    float e4 = __expf(b.x - m), e5 = __expf(b.y - m), e6 = __expf(b.z - m), e7 = __expf(b.w - m);
    float s = ((e0 + e1) + (e2 + e3)) + ((e4 + e5) + (e6 + e7));
    s = block_reduce_sum256(s);
    float inv = 1.0f / s;
    r4[t] = make_float4(e0 * inv, e1 * inv, e2 * inv, e3 * inv);
    r4[t + 256] = make_float4(e4 * inv, e5 * inv, e6 * inv, e7 * inv);
}

// ---------------- launcher ---------------------------------------------------
extern "C" void kernel_launch(void* const* d_in, const int* in_sizes, int n_in,
                              void* d_out, int out_size) {
    (void)in_sizes; (void)n_in; (void)out_size;
    const float* X  = (const float*)d_in[0];
    const float* W  = (const float*)d_in[1];
    const float* W1 = (const float*)d_in[2];
    const float* b1 = (const float*)d_in[3];
    const float* W2 = (const float*)d_in[4];
    const float* b2 = (const float*)d_in[5];
    const float* W3 = (const float*)d_in[6];
    const float* b3 = (const float*)d_in[7];
    float* out = (float*)d_out;

    prep_kernel<<<8256, 256>>>(X, W);        // split X || single-pass W stats
    dim3 gm(64, 64);
    mlp_kernel<<<gm, 256>>>(W, W1, b1, W2, b2, W3, b3);

    cudaFuncSetAttribute(gemm_kernel, cudaFuncAttributeMaxDynamicSharedMemorySize,
                         SMEM_BYTES);
    dim3 gg(16, 64); // x = N tiles fast -> CTAs in a wave share the A row strip
    gemm_kernel<<<gg, 256, SMEM_BYTES>>>(out);

    softmax_kernel<<<8192, 256>>>(out);
}

// round 16
// speedup vs baseline: 1.0239x; 1.0239x over previous
#include <cuda_runtime.h>
#include <cuda_fp16.h>
#include <stdint.h>
#include <stddef.h>

#define B_DIM 8192
#define N_DIM 2048   // GEMM K (rows of weight)
#define M_DIM 2048   // cols of weight

// ---------------- device scratch (no allocation allowed) -------------------
__device__ __align__(16) __half g_Xhi[(size_t)B_DIM * N_DIM];
__device__ __align__(16) __half g_Xlo[(size_t)B_DIM * N_DIM];
__device__ __align__(16) __half g_Whit[(size_t)M_DIM * N_DIM]; // new_weight^T hi: [j][i]
__device__ __align__(16) __half g_Wlot[(size_t)M_DIM * N_DIM]; // new_weight^T lo
__device__ float g_rowsum[N_DIM];
__device__ float g_colpart[64 * M_DIM];

// ---------------- PTX helpers (baseline PTX only, no 'a' features) ---------
__device__ __forceinline__ uint32_t smem_u32(const void* p) {
    uint32_t a;
    asm("{ .reg .u64 t; cvta.to.shared.u64 t, %1; cvt.u32.u64 %0, t; }"
        : "=r"(a) : "l"(p));
    return a;
}
__device__ __forceinline__ void cp16(uint32_t dst, const void* src) {
    unsigned long long g = (unsigned long long)__cvta_generic_to_global(src);
    asm volatile("cp.async.cg.shared.global [%0], [%1], 16;"
                 :: "r"(dst), "l"(g) : "memory");
}
__device__ __forceinline__ void cp_commit() {
    asm volatile("cp.async.commit_group;" ::: "memory");
}
__device__ __forceinline__ void ldsm_x4(uint32_t& r0, uint32_t& r1,
                                        uint32_t& r2, uint32_t& r3, uint32_t addr) {
    asm volatile("ldmatrix.sync.aligned.m8n8.x4.shared.b16 {%0,%1,%2,%3}, [%4];"
                 : "=r"(r0), "=r"(r1), "=r"(r2), "=r"(r3) : "r"(addr));
}
__device__ __forceinline__ void mma16816(float& c0, float& c1, float& c2, float& c3,
                                         uint32_t a0, uint32_t a1, uint32_t a2, uint32_t a3,
                                         uint32_t b0, uint32_t b1) {
    asm volatile(
        "mma.sync.aligned.m16n8k16.row.col.f32.f16.f16.f32 "
        "{%0,%1,%2,%3}, {%4,%5,%6,%7}, {%8,%9}, {%0,%1,%2,%3};"
        : "+f"(c0), "+f"(c1), "+f"(c2), "+f"(c3)
        : "r"(a0), "r"(a1), "r"(a2), "r"(a3), "r"(b0), "r"(b1));
}

// ---------------- reductions -------------------------------------------------
__device__ __forceinline__ float block_reduce_sum256(float v) {
    __shared__ float s[8];
#pragma unroll
    for (int o = 16; o; o >>= 1) v += __shfl_xor_sync(0xffffffffu, v, o);
    if ((threadIdx.x & 31) == 0) s[threadIdx.x >> 5] = v;
    __syncthreads();
    if (threadIdx.x < 32) {
        float t = (threadIdx.x < 8) ? s[threadIdx.x] : 0.0f;
#pragma unroll
        for (int o = 4; o; o >>= 1) t += __shfl_xor_sync(0xffffffffu, t, o);
        if (threadIdx.x == 0) s[0] = t;
    }
    __syncthreads();
    float r = s[0];
    __syncthreads();
    return r;
}
__device__ __forceinline__ float block_reduce_max256(float v) {
    __shared__ float s[8];
#pragma unroll
    for (int o = 16; o; o >>= 1) v = fmaxf(v, __shfl_xor_sync(0xffffffffu, v, o));
    if ((threadIdx.x & 31) == 0) s[threadIdx.x >> 5] = v;
    __syncthreads();
    if (threadIdx.x < 32) {
        float t = (threadIdx.x < 8) ? s[threadIdx.x] : -3.402823466e38f;
#pragma unroll
        for (int o = 4; o; o >>= 1) t = fmaxf(t, __shfl_xor_sync(0xffffffffu, t, o));
        if (threadIdx.x == 0) s[0] = t;
    }
    __syncthreads();
    float r = s[0];
    __syncthreads();
    return r;
}

// ---------------- fused prep: col partials || row sums || split X -----------
// Heavy low-parallelism blocks FIRST so they overlap the xsplit bulk:
// blocks [0,64):        column partial sums of W (32 rows per block)
// blocks [64,2112):     row sums of W
// blocks [2112,10304):  split X into hi/lo fp16
__global__ void __launch_bounds__(256) prep_kernel(const float* __restrict__ X,
                                                   const float* __restrict__ W) {
    int bid = blockIdx.x;
    if (bid < 64) {
        int pb = bid;
        float acc[8] = {0, 0, 0, 0, 0, 0, 0, 0};
        int r0 = pb * 32;
        for (int i = 0; i < 32; i++) {
            const float* row = W + (size_t)(r0 + i) * M_DIM;
#pragma unroll
            for (int u = 0; u < 8; u++) acc[u] += row[u * 256 + threadIdx.x];
        }
#pragma unroll
        for (int u = 0; u < 8; u++)
            g_colpart[pb * M_DIM + u * 256 + threadIdx.x] = acc[u];
    } else if (bid < 2112) {
        int r = bid - 64;
        const float* row = W + (size_t)r * M_DIM;
        float s = 0.0f;
        for (int j = threadIdx.x; j < M_DIM; j += 256) s += row[j];
        s = block_reduce_sum256(s);
        if (threadIdx.x == 0) g_rowsum[r] = s;
    } else {
        size_t idx = (size_t)(bid - 2112) * 256 + threadIdx.x; // one idx = 8 elems
        const float4* x4 = (const float4*)X;
        float4 a = x4[idx * 2 + 0];
        float4 b = x4[idx * 2 + 1];
        float v[8] = {a.x, a.y, a.z, a.w, b.x, b.y, b.z, b.w};
        union U { __half h[8]; uint4 u; } uh, ul;
#pragma unroll
        for (int i = 0; i < 8; i++) {
            __half hi = __float2half_rn(v[i]);
            uh.h[i] = hi;
            ul.h[i] = __float2half_rn(v[i] - __half2float(hi));
        }
        ((uint4*)g_Xhi)[idx] = uh.u;
        ((uint4*)g_Xlo)[idx] = ul.u;
    }
}

// per-cell MLP -> new_weight (hi/lo fp16), stored TRANSPOSED ([j][i], K-major B)
// col sums reduced in-block from g_colpart; 4 cells/thread processed together.
__global__ void __launch_bounds__(256) mlp_kernel(
    const float* __restrict__ W,
    const float* __restrict__ W1, const float* __restrict__ b1,
    const float* __restrict__ W2, const float* __restrict__ b2,
    const float* __restrict__ W3, const float* __restrict__ b3) {
    __shared__ float sW1[30], sb1[10], sW2[100], sb2[10], sW3[10], sb3v[1];
    __shared__ float sColP[8][32], sCol[32];
    __shared__ __half shi[32][33], slo[32][33];
    int t = threadIdx.x;
    int tj = t & 31, ti = t >> 5;
    int i0 = blockIdx.y * 32, j0 = blockIdx.x * 32;
    if (t < 30) sW1[t] = W1[t];
    if (t < 10) { sb1[t] = b1[t]; sb2[t] = b2[t]; sW3[t] = W3[t]; }
    if (t >= 32 && t < 132) sW2[t - 32] = W2[t - 32];
    if (t == 0) sb3v[0] = b3[0];
    {
        float p = 0.0f;
#pragma unroll
        for (int b = 0; b < 8; b++) p += g_colpart[(ti + 8 * b) * M_DIM + j0 + tj];
        sColP[ti][tj] = p;
    }
    __syncthreads();
    if (t < 32) {
        float s = 0.0f;
#pragma unroll
        for (int b = 0; b < 8; b++) s += sColP[b][t];
        sCol[t] = s;
    }
    __syncthreads();

    float w[4], f1[4], f2[4], h1[4][10];
#pragma unroll
    for (int rr = 0; rr < 4; rr++) {
        int il = ti + 8 * rr;
        int i = i0 + il, j = j0 + tj;
        w[rr] = W[(size_t)i * M_DIM + j];
        f1[rr] = (sCol[tj] - w[rr]) * (1.0f / 2047.0f);     // fwd (LOO col mean)
        f2[rr] = (g_rowsum[i] - w[rr]) * (1.0f / 2047.0f);  // bwd (LOO row mean)
    }
#pragma unroll
    for (int k = 0; k < 10; k++) {
        float wa = sW1[k], wb = sW1[10 + k], wc = sW1[20 + k], bb = sb1[k];
#pragma unroll
        for (int rr = 0; rr < 4; rr++)
            h1[rr][k] = fmaxf(0.f, w[rr] * wa + f1[rr] * wb + f2[rr] * wc + bb);
    }
    float u[4];
#pragma unroll
    for (int rr = 0; rr < 4; rr++) u[rr] = sb3v[0];
#pragma unroll
    for (int k = 0; k < 10; k++) {
        float a0 = sb2[k], a1v = sb2[k], a2 = sb2[k], a3 = sb2[k];
#pragma unroll
        for (int l = 0; l < 10; l++) {
            float wkl = sW2[l * 10 + k];
            a0 += h1[0][l] * wkl;
            a1v += h1[1][l] * wkl;
            a2 += h1[2][l] * wkl;
            a3 += h1[3][l] * wkl;
        }
        float w3k = sW3[k];
        u[0] += fmaxf(0.f, a0) * w3k;
        u[1] += fmaxf(0.f, a1v) * w3k;
        u[2] += fmaxf(0.f, a2) * w3k;
        u[3] += fmaxf(0.f, a3) * w3k;
    }
#pragma unroll
    for (int rr = 0; rr < 4; rr++) {
        int il = ti + 8 * rr;
        float nw = w[rr] + u[rr];
        __half hi = __float2half_rn(nw);
        shi[il][tj] = hi;
        slo[il][tj] = __float2half_rn(nw - __half2float(hi));
    }
    __syncthreads();
#pragma unroll
    for (int rr = 0; rr < 4; rr++) {
        int jl = ti + 8 * rr, il = tj;
        size_t off = (size_t)(j0 + jl) * N_DIM + i0 + il;
        g_Whit[off] = shi[il][jl];
        g_Wlot[off] = slo[il][jl];
    }
}

// ---------------- GEMM: Y = X @ Wnew via fused fp16x3 split (R10 proven) ----
#define KSTAGE 64
#define PITCHB 144                  // 64 halves (128B) + 16B pad
#define OPB (128 * PITCHB)          // 18432 per operand per stage
#define STGBYTES (4 * OPB)          // 73728 per stage
#define NST 3
#define SMEM_BYTES (NST * STGBYTES) // 221184
#define NSTAGES_TOT 32              // 2048 / 64

__device__ __forceinline__ uint32_t stage_base(int s, uint32_t sb) {
    return sb + (s % NST) * STGBYTES;
}

// one quarter (4 cp16/thread) of a stage's loads; NO commit
__device__ __forceinline__ void load_quarter(int s, int q, int t, int m0, int n0,
                                             uint32_t sb) {
    int kk = s * KSTAGE;
    uint32_t base = stage_base(s, sb);
    int idx = t + q * 256;
    int row = idx >> 3, kc = idx & 7;
    uint32_t so = row * PITCHB + kc * 16;
    size_t goA = (size_t)(m0 + row) * N_DIM + kk + kc * 8;
    size_t goB = (size_t)(n0 + row) * N_DIM + kk + kc * 8;
    cp16(base + 0 * OPB + so, g_Xhi + goA);
    cp16(base + 1 * OPB + so, g_Xlo + goA);
    cp16(base + 2 * OPB + so, g_Whit + goB);
    cp16(base + 3 * OPB + so, g_Wlot + goB);
}

__device__ __forceinline__ void load_stage(int s, int t, int m0, int n0, uint32_t sb) {
#pragma unroll
    for (int q = 0; q < 4; q++) load_quarter(s, q, t, m0, n0, sb);
    cp_commit();
}

#define LOAD_FRAGS(buf, bs, kofs) do {                                             \
    _Pragma("unroll")                                                              \
    for (int mi_ = 0; mi_ < 4; mi_++) {                                            \
        uint32_t ar_ = (a_row + mi_ * 16) * PITCHB + a_koff + (kofs);              \
        ldsm_x4(ahi[buf][mi_][0], ahi[buf][mi_][1], ahi[buf][mi_][2],              \
                ahi[buf][mi_][3], (bs) + 0 * OPB + ar_);                           \
        ldsm_x4(alo[buf][mi_][0], alo[buf][mi_][1], alo[buf][mi_][2],              \
                alo[buf][mi_][3], (bs) + 1 * OPB + ar_);                           \
    }                                                                              \
    _Pragma("unroll")                                                              \
    for (int bi_ = 0; bi_ < 2; bi_++) {                                            \
        uint32_t br_ = (b_row + bi_ * 16) * PITCHB + b_koff + (kofs);              \
        ldsm_x4(bhi[buf][2 * bi_][0], bhi[buf][2 * bi_][1],                        \
                bhi[buf][2 * bi_ + 1][0], bhi[buf][2 * bi_ + 1][1],                \
                (bs) + 2 * OPB + br_);                                             \
        ldsm_x4(blo[buf][2 * bi_][0], blo[buf][2 * bi_][1],                        \
                blo[buf][2 * bi_ + 1][0], blo[buf][2 * bi_ + 1][1],                \
                (bs) + 3 * OPB + br_);                                             \
    }                                                                              \
} while (0)

#define DO_MMAS(buf) do {                                                          \
    _Pragma("unroll")                                                              \
    for (int mi = 0; mi < 4; mi++)                                                 \
        _Pragma("unroll")                                                          \
        for (int ni = 0; ni < 4; ni++)                                             \
            mma16816(acc[mi][ni][0], acc[mi][ni][1], acc[mi][ni][2], acc[mi][ni][3], \
                     ahi[buf][mi][0], ahi[buf][mi][1], ahi[buf][mi][2], ahi[buf][mi][3], \
                     bhi[buf][ni][0], bhi[buf][ni][1]);                            \
    _Pragma("unroll")                                                              \
    for (int mi = 0; mi < 4; mi++)                                                 \
        _Pragma("unroll")                                                          \
        for (int ni = 0; ni < 4; ni++)                                             \
            mma16816(acc[mi][ni][0], acc[mi][ni][1], acc[mi][ni][2], acc[mi][ni][3], \
                     ahi[buf][mi][0], ahi[buf][mi][1], ahi[buf][mi][2], ahi[buf][mi][3], \
                     blo[buf][ni][0], blo[buf][ni][1]);                            \
    _Pragma("unroll")                                                              \
    for (int mi = 0; mi < 4; mi++)                                                 \
        _Pragma("unroll")                                                          \
        for (int ni = 0; ni < 4; ni++)                                             \
            mma16816(acc[mi][ni][0], acc[mi][ni][1], acc[mi][ni][2], acc[mi][ni][3], \
                     alo[buf][mi][0], alo[buf][mi][1], alo[buf][mi][2], alo[buf][mi][3], \
                     bhi[buf][ni][0], bhi[buf][ni][1]);                            \
} while (0)

__global__ void __launch_bounds__(256, 1) gemm_kernel(float* __restrict__ Y) {
    extern __shared__ char smem[];
    uint32_t sb = smem_u32(smem);
    int t = threadIdx.x;
    int lane = t & 31, wid = t >> 5;
    int wm = wid >> 2, wn = wid & 3;             // warp tile origin: (wm*64, wn*32)
    int n0 = blockIdx.x * 128, m0 = blockIdx.y * 128;

    float acc[4][4][4];
#pragma unroll
    for (int i = 0; i < 4; i++)
#pragma unroll
        for (int j = 0; j < 4; j++)
#pragma unroll
            for (int k = 0; k < 4; k++) acc[i][j][k] = 0.0f;

    load_stage(0, t, m0, n0, sb);
    load_stage(1, t, m0, n0, sb);

    uint32_t a_row = wm * 64 + (lane & 15);
    uint32_t a_koff = (lane >> 4) << 4;
    uint32_t b_row = wn * 32 + ((lane >> 3) >> 1) * 8 + (lane & 7);
    uint32_t b_koff = ((lane >> 3) & 1) << 4;

    uint32_t ahi[2][4][4], alo[2][4][4], bhi[2][4][2], blo[2][4][2];

    asm volatile("cp.async.wait_group 1;" ::: "memory"); // stage 0 resident
    __syncthreads();
    LOAD_FRAGS(0, sb, 0);

    int cur = 0;
#pragma unroll 1
    for (int s = 0; s < NSTAGES_TOT; s++) {
        uint32_t bs = stage_base(s, sb);
        uint32_t bsn = stage_base(s + 1, sb);
#pragma unroll
        for (int ks = 0; ks < 3; ks++) {
            if (s + 2 < NSTAGES_TOT) load_quarter(s + 2, ks, t, m0, n0, sb);
            int nxt = cur ^ 1;
            LOAD_FRAGS(nxt, bs, (ks + 1) * 32);
            DO_MMAS(cur);
            cur = nxt;
        }
        if (s + 2 < NSTAGES_TOT) load_quarter(s + 2, 3, t, m0, n0, sb);
        cp_commit();
        asm volatile("cp.async.wait_group 1;" ::: "memory");
        __syncthreads();
        {
            int nxt = cur ^ 1;
            if (s + 1 < NSTAGES_TOT) LOAD_FRAGS(nxt, bsn, 0);
            DO_MMAS(cur);
            cur = nxt;
        }
    }

    int r_base = m0 + wm * 64 + (lane >> 2);
    int c_base = n0 + wn * 32 + 2 * (lane & 3);
#pragma unroll
    for (int mi = 0; mi < 4; mi++)
#pragma unroll
        for (int ni = 0; ni < 4; ni++) {
            size_t off0 = (size_t)(r_base + mi * 16) * M_DIM + c_base + ni * 8;
            *(float2*)(Y + off0) = make_float2(acc[mi][ni][0], acc[mi][ni][1]);
            *(float2*)(Y + off0 + 8 * M_DIM) = make_float2(acc[mi][ni][2], acc[mi][ni][3]);
        }
}

// ---------------- softmax (in-place on Y rows) -------------------------------
__global__ void __launch_bounds__(256) softmax_kernel(float* __restrict__ Y) {
    float4* r4 = (float4*)(Y + (size_t)blockIdx.x * M_DIM);
    int t = threadIdx.x;
    float4 a = r4[t], b = r4[t + 256];
    float m = fmaxf(fmaxf(fmaxf(a.x, a.y), fmaxf(a.z, a.w)),
                    fmaxf(fmaxf(b.x, b.y), fmaxf(b.z, b.w)));
    m = block_reduce_max256(m);
    float e0 = __expf(a.x - m), e1 = __expf(a.y - m), e2 = __expf(a.z - m), e3 = __expf(a.w - m);
    float e4 = __expf(b.x - m), e5 = __expf(b.y - m), e6 = __expf(b.z - m), e7 = __expf(b.w - m);
    float s = ((e0 + e1) + (e2 + e3)) + ((e4 + e5) + (e6 + e7));
    s = block_reduce_sum256(s);
    float inv = 1.0f / s;
    r4[t] = make_float4(e0 * inv, e1 * inv, e2 * inv, e3 * inv);
    r4[t + 256] = make_float4(e4 * inv, e5 * inv, e6 * inv, e7 * inv);
}

// ---------------- launcher ---------------------------------------------------
extern "C" void kernel_launch(void* const* d_in, const int* in_sizes, int n_in,
                              void* d_out, int out_size) {
    (void)in_sizes; (void)n_in; (void)out_size;
    const float* X  = (const float*)d_in[0];
    const float* W  = (const float*)d_in[1];
    const float* W1 = (const float*)d_in[2];
    const float* b1 = (const float*)d_in[3];
    const float* W2 = (const float*)d_in[4];
    const float* b2 = (const float*)d_in[5];
    const float* W3 = (const float*)d_in[6];
    const float* b3 = (const float*)d_in[7];
    float* out = (float*)d_out;

    prep_kernel<<<10304, 256>>>(X, W);       // colpart || rowsum || split X
    dim3 gm(64, 64);
    mlp_kernel<<<gm, 256>>>(W, W1, b1, W2, b2, W3, b3);

    cudaFuncSetAttribute(gemm_kernel, cudaFuncAttributeMaxDynamicSharedMemorySize,
                         SMEM_BYTES);
    dim3 gg(16, 64); // x = N tiles fast -> CTAs in a wave share the A row strip
    gemm_kernel<<<gg, 256, SMEM_BYTES>>>(out);

    softmax_kernel<<<8192, 256>>>(out);
}

// round 17
// speedup vs baseline: 1.0370x; 1.0128x over previous
#include <cuda_runtime.h>
#include <cuda_fp16.h>
#include <stdint.h>
#include <stddef.h>

#define B_DIM 8192
#define N_DIM 2048   // GEMM K (rows of weight)
#define M_DIM 2048   // cols of weight

// ---------------- device scratch (no allocation allowed) -------------------
__device__ __align__(16) __half g_Xhi[(size_t)B_DIM * N_DIM];
__device__ __align__(16) __half g_Xlo[(size_t)B_DIM * N_DIM];
__device__ __align__(16) __half g_Whit[(size_t)M_DIM * N_DIM]; // new_weight^T hi: [j][i]
__device__ __align__(16) __half g_Wlot[(size_t)M_DIM * N_DIM]; // new_weight^T lo
__device__ float g_rowsum[N_DIM];
__device__ float g_colpart[64 * M_DIM];

// ---------------- PTX helpers (baseline PTX only, no 'a' features) ---------
__device__ __forceinline__ uint32_t smem_u32(const void* p) {
    uint32_t a;
    asm("{ .reg .u64 t; cvta.to.shared.u64 t, %1; cvt.u32.u64 %0, t; }"
        : "=r"(a) : "l"(p));
    return a;
}
__device__ __forceinline__ void cp16(uint32_t dst, const void* src) {
    unsigned long long g = (unsigned long long)__cvta_generic_to_global(src);
    asm volatile("cp.async.cg.shared.global [%0], [%1], 16;"
                 :: "r"(dst), "l"(g) : "memory");
}
__device__ __forceinline__ void cp_commit() {
    asm volatile("cp.async.commit_group;" ::: "memory");
}
__device__ __forceinline__ void ldsm_x4(uint32_t& r0, uint32_t& r1,
                                        uint32_t& r2, uint32_t& r3, uint32_t addr) {
    asm volatile("ldmatrix.sync.aligned.m8n8.x4.shared.b16 {%0,%1,%2,%3}, [%4];"
                 : "=r"(r0), "=r"(r1), "=r"(r2), "=r"(r3) : "r"(addr));
}
__device__ __forceinline__ void mma16816(float& c0, float& c1, float& c2, float& c3,
                                         uint32_t a0, uint32_t a1, uint32_t a2, uint32_t a3,
                                         uint32_t b0, uint32_t b1) {
    asm volatile(
        "mma.sync.aligned.m16n8k16.row.col.f32.f16.f16.f32 "
        "{%0,%1,%2,%3}, {%4,%5,%6,%7}, {%8,%9}, {%0,%1,%2,%3};"
        : "+f"(c0), "+f"(c1), "+f"(c2), "+f"(c3)
        : "r"(a0), "r"(a1), "r"(a2), "r"(a3), "r"(b0), "r"(b1));
}

// ---------------- reductions -------------------------------------------------
__device__ __forceinline__ float block_reduce_sum256(float v) {
    __shared__ float s[8];
#pragma unroll
    for (int o = 16; o; o >>= 1) v += __shfl_xor_sync(0xffffffffu, v, o);
    if ((threadIdx.x & 31) == 0) s[threadIdx.x >> 5] = v;
    __syncthreads();
    if (threadIdx.x < 32) {
        float t = (threadIdx.x < 8) ? s[threadIdx.x] : 0.0f;
#pragma unroll
        for (int o = 4; o; o >>= 1) t += __shfl_xor_sync(0xffffffffu, t, o);
        if (threadIdx.x == 0) s[0] = t;
    }
    __syncthreads();
    float r = s[0];
    __syncthreads();
    return r;
}
__device__ __forceinline__ float block_reduce_max256(float v) {
    __shared__ float s[8];
#pragma unroll
    for (int o = 16; o; o >>= 1) v = fmaxf(v, __shfl_xor_sync(0xffffffffu, v, o));
    if ((threadIdx.x & 31) == 0) s[threadIdx.x >> 5] = v;
    __syncthreads();
    if (threadIdx.x < 32) {
        float t = (threadIdx.x < 8) ? s[threadIdx.x] : -3.402823466e38f;
#pragma unroll
        for (int o = 4; o; o >>= 1) t = fmaxf(t, __shfl_xor_sync(0xffffffffu, t, o));
        if (threadIdx.x == 0) s[0] = t;
    }
    __syncthreads();
    float r = s[0];
    __syncthreads();
    return r;
}

// ---------------- fused prep: col partials || row sums || split X -----------
// Heavy low-parallelism blocks FIRST so they overlap the xsplit bulk:
// blocks [0,64):        column partial sums of W (32 rows per block)
// blocks [64,2112):     row sums of W
// blocks [2112,10304):  split X into hi/lo fp16
__global__ void __launch_bounds__(256) prep_kernel(const float* __restrict__ X,
                                                   const float* __restrict__ W) {
    int bid = blockIdx.x;
    if (bid < 64) {
        int pb = bid;
        float acc[8] = {0, 0, 0, 0, 0, 0, 0, 0};
        int r0 = pb * 32;
        for (int i = 0; i < 32; i++) {
            const float* row = W + (size_t)(r0 + i) * M_DIM;
#pragma unroll
            for (int u = 0; u < 8; u++) acc[u] += row[u * 256 + threadIdx.x];
        }
#pragma unroll
        for (int u = 0; u < 8; u++)
            g_colpart[pb * M_DIM + u * 256 + threadIdx.x] = acc[u];
    } else if (bid < 2112) {
        int r = bid - 64;
        const float* row = W + (size_t)r * M_DIM;
        float s = 0.0f;
        for (int j = threadIdx.x; j < M_DIM; j += 256) s += row[j];
        s = block_reduce_sum256(s);
        if (threadIdx.x == 0) g_rowsum[r] = s;
    } else {
        size_t idx = (size_t)(bid - 2112) * 256 + threadIdx.x; // one idx = 8 elems
        const float4* x4 = (const float4*)X;
        float4 a = x4[idx * 2 + 0];
        float4 b = x4[idx * 2 + 1];
        float v[8] = {a.x, a.y, a.z, a.w, b.x, b.y, b.z, b.w};
        union U { __half h[8]; uint4 u; } uh, ul;
#pragma unroll
        for (int i = 0; i < 8; i++) {
            __half hi = __float2half_rn(v[i]);
            uh.h[i] = hi;
            ul.h[i] = __float2half_rn(v[i] - __half2float(hi));
        }
        ((uint4*)g_Xhi)[idx] = uh.u;
        ((uint4*)g_Xlo)[idx] = ul.u;
    }
}

// per-cell MLP -> new_weight (hi/lo fp16), stored TRANSPOSED ([j][i], K-major B)
// col sums reduced in-block from g_colpart; 4 cells/thread processed together.
__global__ void __launch_bounds__(256) mlp_kernel(
    const float* __restrict__ W,
    const float* __restrict__ W1, const float* __restrict__ b1,
    const float* __restrict__ W2, const float* __restrict__ b2,
    const float* __restrict__ W3, const float* __restrict__ b3) {
    __shared__ float sW1[30], sb1[10], sW2[100], sb2[10], sW3[10], sb3v[1];
    __shared__ float sColP[8][32], sCol[32];
    __shared__ __half shi[32][33], slo[32][33];
    int t = threadIdx.x;
    int tj = t & 31, ti = t >> 5;
    int i0 = blockIdx.y * 32, j0 = blockIdx.x * 32;
    if (t < 30) sW1[t] = W1[t];
    if (t < 10) { sb1[t] = b1[t]; sb2[t] = b2[t]; sW3[t] = W3[t]; }
    if (t >= 32 && t < 132) sW2[t - 32] = W2[t - 32];
    if (t == 0) sb3v[0] = b3[0];
    {
        float p = 0.0f;
#pragma unroll
        for (int b = 0; b < 8; b++) p += g_colpart[(ti + 8 * b) * M_DIM + j0 + tj];
        sColP[ti][tj] = p;
    }
    __syncthreads();
    if (t < 32) {
        float s = 0.0f;
#pragma unroll
        for (int b = 0; b < 8; b++) s += sColP[b][t];
        sCol[t] = s;
    }
    __syncthreads();

    float w[4], f1[4], f2[4], h1[4][10];
#pragma unroll
    for (int rr = 0; rr < 4; rr++) {
        int il = ti + 8 * rr;
        int i = i0 + il, j = j0 + tj;
        w[rr] = W[(size_t)i * M_DIM + j];
        f1[rr] = (sCol[tj] - w[rr]) * (1.0f / 2047.0f);     // fwd (LOO col mean)
        f2[rr] = (g_rowsum[i] - w[rr]) * (1.0f / 2047.0f);  // bwd (LOO row mean)
    }
#pragma unroll
    for (int k = 0; k < 10; k++) {
        float wa = sW1[k], wb = sW1[10 + k], wc = sW1[20 + k], bb = sb1[k];
#pragma unroll
        for (int rr = 0; rr < 4; rr++)
            h1[rr][k] = fmaxf(0.f, w[rr] * wa + f1[rr] * wb + f2[rr] * wc + bb);
    }
    float u[4];
#pragma unroll
    for (int rr = 0; rr < 4; rr++) u[rr] = sb3v[0];
#pragma unroll
    for (int k = 0; k < 10; k++) {
        float a0 = sb2[k], a1v = sb2[k], a2 = sb2[k], a3 = sb2[k];
#pragma unroll
        for (int l = 0; l < 10; l++) {
            float wkl = sW2[l * 10 + k];
            a0 += h1[0][l] * wkl;
            a1v += h1[1][l] * wkl;
            a2 += h1[2][l] * wkl;
            a3 += h1[3][l] * wkl;
        }
        float w3k = sW3[k];
        u[0] += fmaxf(0.f, a0) * w3k;
        u[1] += fmaxf(0.f, a1v) * w3k;
        u[2] += fmaxf(0.f, a2) * w3k;
        u[3] += fmaxf(0.f, a3) * w3k;
    }
#pragma unroll
    for (int rr = 0; rr < 4; rr++) {
        int il = ti + 8 * rr;
        float nw = w[rr] + u[rr];
        __half hi = __float2half_rn(nw);
        shi[il][tj] = hi;
        slo[il][tj] = __float2half_rn(nw - __half2float(hi));
    }
    __syncthreads();
#pragma unroll
    for (int rr = 0; rr < 4; rr++) {
        int jl = ti + 8 * rr, il = tj;
        size_t off = (size_t)(j0 + jl) * N_DIM + i0 + il;
        g_Whit[off] = shi[il][jl];
        g_Wlot[off] = slo[il][jl];
    }
}

// ---------------- GEMM: Y = X @ Wnew via fused fp16x3 split (R10 proven) ----
#define KSTAGE 64
#define PITCHB 144                  // 64 halves (128B) + 16B pad
#define OPB (128 * PITCHB)          // 18432 per operand per stage
#define STGBYTES (4 * OPB)          // 73728 per stage
#define NST 3
#define SMEM_BYTES (NST * STGBYTES) // 221184
#define NSTAGES_TOT 32              // 2048 / 64

__device__ __forceinline__ uint32_t stage_base(int s, uint32_t sb) {
    return sb + (s % NST) * STGBYTES;
}

// one quarter (4 cp16/thread) of a stage's loads; NO commit
__device__ __forceinline__ void load_quarter(int s, int q, int t, int m0, int n0,
                                             uint32_t sb) {
    int kk = s * KSTAGE;
    uint32_t base = stage_base(s, sb);
    int idx = t + q * 256;
    int row = idx >> 3, kc = idx & 7;
    uint32_t so = row * PITCHB + kc * 16;
    size_t goA = (size_t)(m0 + row) * N_DIM + kk + kc * 8;
    size_t goB = (size_t)(n0 + row) * N_DIM + kk + kc * 8;
    cp16(base + 0 * OPB + so, g_Xhi + goA);
    cp16(base + 1 * OPB + so, g_Xlo + goA);
    cp16(base + 2 * OPB + so, g_Whit + goB);
    cp16(base + 3 * OPB + so, g_Wlot + goB);
}

__device__ __forceinline__ void load_stage(int s, int t, int m0, int n0, uint32_t sb) {
#pragma unroll
    for (int q = 0; q < 4; q++) load_quarter(s, q, t, m0, n0, sb);
    cp_commit();
}

#define LOAD_FRAGS(buf, bs, kofs) do {                                             \
    _Pragma("unroll")                                                              \
    for (int mi_ = 0; mi_ < 4; mi_++) {                                            \
        uint32_t ar_ = (a_row + mi_ * 16) * PITCHB + a_koff + (kofs);              \
        ldsm_x4(ahi[buf][mi_][0], ahi[buf][mi_][1], ahi[buf][mi_][2],              \
                ahi[buf][mi_][3], (bs) + 0 * OPB + ar_);                           \
        ldsm_x4(alo[buf][mi_][0], alo[buf][mi_][1], alo[buf][mi_][2],              \
                alo[buf][mi_][3], (bs) + 1 * OPB + ar_);                           \
    }                                                                              \
    _Pragma("unroll")                                                              \
    for (int bi_ = 0; bi_ < 2; bi_++) {                                            \
        uint32_t br_ = (b_row + bi_ * 16) * PITCHB + b_koff + (kofs);              \
        ldsm_x4(bhi[buf][2 * bi_][0], bhi[buf][2 * bi_][1],                        \
                bhi[buf][2 * bi_ + 1][0], bhi[buf][2 * bi_ + 1][1],                \
                (bs) + 2 * OPB + br_);                                             \
        ldsm_x4(blo[buf][2 * bi_][0], blo[buf][2 * bi_][1],                        \
                blo[buf][2 * bi_ + 1][0], blo[buf][2 * bi_ + 1][1],                \
                (bs) + 3 * OPB + br_);                                             \
    }                                                                              \
} while (0)

#define DO_MMAS(buf) do {                                                          \
    _Pragma("unroll")                                                              \
    for (int mi = 0; mi < 4; mi++)                                                 \
        _Pragma("unroll")                                                          \
        for (int ni = 0; ni < 4; ni++)                                             \
            mma16816(acc[mi][ni][0], acc[mi][ni][1], acc[mi][ni][2], acc[mi][ni][3], \
                     ahi[buf][mi][0], ahi[buf][mi][1], ahi[buf][mi][2], ahi[buf][mi][3], \
                     bhi[buf][ni][0], bhi[buf][ni][1]);                            \
    _Pragma("unroll")                                                              \
    for (int mi = 0; mi < 4; mi++)                                                 \
        _Pragma("unroll")                                                          \
        for (int ni = 0; ni < 4; ni++)                                             \
            mma16816(acc[mi][ni][0], acc[mi][ni][1], acc[mi][ni][2], acc[mi][ni][3], \
                     ahi[buf][mi][0], ahi[buf][mi][1], ahi[buf][mi][2], ahi[buf][mi][3], \
                     blo[buf][ni][0], blo[buf][ni][1]);                            \
    _Pragma("unroll")                                                              \
    for (int mi = 0; mi < 4; mi++)                                                 \
        _Pragma("unroll")                                                          \
        for (int ni = 0; ni < 4; ni++)                                             \
            mma16816(acc[mi][ni][0], acc[mi][ni][1], acc[mi][ni][2], acc[mi][ni][3], \
                     alo[buf][mi][0], alo[buf][mi][1], alo[buf][mi][2], alo[buf][mi][3], \
                     bhi[buf][ni][0], bhi[buf][ni][1]);                            \
} while (0)

__global__ void __launch_bounds__(256, 1) gemm_kernel(float* __restrict__ Y, int mbase) {
    extern __shared__ char smem[];
    uint32_t sb = smem_u32(smem);
    int t = threadIdx.x;
    int lane = t & 31, wid = t >> 5;
    int wm = wid >> 2, wn = wid & 3;             // warp tile origin: (wm*64, wn*32)
    int n0 = blockIdx.x * 128, m0 = (blockIdx.y + mbase) * 128;

    float acc[4][4][4];
#pragma unroll
    for (int i = 0; i < 4; i++)
#pragma unroll
        for (int j = 0; j < 4; j++)
#pragma unroll
            for (int k = 0; k < 4; k++) acc[i][j][k] = 0.0f;

    load_stage(0, t, m0, n0, sb);
    load_stage(1, t, m0, n0, sb);

    uint32_t a_row = wm * 64 + (lane & 15);
    uint32_t a_koff = (lane >> 4) << 4;
    uint32_t b_row = wn * 32 + ((lane >> 3) >> 1) * 8 + (lane & 7);
    uint32_t b_koff = ((lane >> 3) & 1) << 4;

    uint32_t ahi[2][4][4], alo[2][4][4], bhi[2][4][2], blo[2][4][2];

    asm volatile("cp.async.wait_group 1;" ::: "memory"); // stage 0 resident
    __syncthreads();
    LOAD_FRAGS(0, sb, 0);

    int cur = 0;
#pragma unroll 1
    for (int s = 0; s < NSTAGES_TOT; s++) {
        uint32_t bs = stage_base(s, sb);
        uint32_t bsn = stage_base(s + 1, sb);
#pragma unroll
        for (int ks = 0; ks < 3; ks++) {
            if (s + 2 < NSTAGES_TOT) load_quarter(s + 2, ks, t, m0, n0, sb);
            int nxt = cur ^ 1;
            LOAD_FRAGS(nxt, bs, (ks + 1) * 32);
            DO_MMAS(cur);
            cur = nxt;
        }
        if (s + 2 < NSTAGES_TOT) load_quarter(s + 2, 3, t, m0, n0, sb);
        cp_commit();
        asm volatile("cp.async.wait_group 1;" ::: "memory");
        __syncthreads();
        {
            int nxt = cur ^ 1;
            if (s + 1 < NSTAGES_TOT) LOAD_FRAGS(nxt, bsn, 0);
            DO_MMAS(cur);
            cur = nxt;
        }
    }

    int r_base = m0 + wm * 64 + (lane >> 2);
    int c_base = n0 + wn * 32 + 2 * (lane & 3);
#pragma unroll
    for (int mi = 0; mi < 4; mi++)
#pragma unroll
        for (int ni = 0; ni < 4; ni++) {
            size_t off0 = (size_t)(r_base + mi * 16) * M_DIM + c_base + ni * 8;
            *(float2*)(Y + off0) = make_float2(acc[mi][ni][0], acc[mi][ni][1]);
            *(float2*)(Y + off0 + 8 * M_DIM) = make_float2(acc[mi][ni][2], acc[mi][ni][3]);
        }
}

// ---------------- softmax (in-place on Y rows) -------------------------------
__global__ void __launch_bounds__(256) softmax_kernel(float* __restrict__ Y, int rowbase) {
    float4* r4 = (float4*)(Y + (size_t)(blockIdx.x + rowbase) * M_DIM);
    int t = threadIdx.x;
    float4 a = r4[t], b = r4[t + 256];
    float m = fmaxf(fmaxf(fmaxf(a.x, a.y), fmaxf(a.z, a.w)),
                    fmaxf(fmaxf(b.x, b.y), fmaxf(b.z, b.w)));
    m = block_reduce_max256(m);
    float e0 = __expf(a.x - m), e1 = __expf(a.y - m), e2 = __expf(a.z - m), e3 = __expf(a.w - m);
    float e4 = __expf(b.x - m), e5 = __expf(b.y - m), e6 = __expf(b.z - m), e7 = __expf(b.w - m);
    float s = ((e0 + e1) + (e2 + e3)) + ((e4 + e5) + (e6 + e7));
    s = block_reduce_sum256(s);
    float inv = 1.0f / s;
    r4[t] = make_float4(e0 * inv, e1 * inv, e2 * inv, e3 * inv);
    r4[t + 256] = make_float4(e4 * inv, e5 * inv, e6 * inv, e7 * inv);
}

// ---------------- launcher ---------------------------------------------------
extern "C" void kernel_launch(void* const* d_in, const int* in_sizes, int n_in,
                              void* d_out, int out_size) {
    (void)in_sizes; (void)n_in; (void)out_size;
    const float* X  = (const float*)d_in[0];
    const float* W  = (const float*)d_in[1];
    const float* W1 = (const float*)d_in[2];
    const float* b1 = (const float*)d_in[3];
    const float* W2 = (const float*)d_in[4];
    const float* b2 = (const float*)d_in[5];
    const float* W3 = (const float*)d_in[6];
    const float* b3 = (const float*)d_in[7];
    float* out = (float*)d_out;

    // lazily create side stream + events (first call = uncaptured correctness run)
    static cudaStream_t s_aux = 0;
    static cudaEvent_t e1 = 0, e2 = 0;
    static int aux_ok = -1;
    if (aux_ok < 0) {
        aux_ok = 1;
        if (cudaStreamCreateWithFlags(&s_aux, cudaStreamNonBlocking) != cudaSuccess)
            aux_ok = 0;
        if (aux_ok && cudaEventCreateWithFlags(&e1, cudaEventDisableTiming) != cudaSuccess)
            aux_ok = 0;
        if (aux_ok && cudaEventCreateWithFlags(&e2, cudaEventDisableTiming) != cudaSuccess)
            aux_ok = 0;
    }

    prep_kernel<<<10304, 256>>>(X, W);       // colpart || rowsum || split X
    dim3 gm(64, 64);
    mlp_kernel<<<gm, 256>>>(W, W1, b1, W2, b2, W3, b3);

    cudaFuncSetAttribute(gemm_kernel, cudaFuncAttributeMaxDynamicSharedMemorySize,
                         SMEM_BYTES);

    if (aux_ok) {
        // GEMM split 55/9 M-strips; softmax of the first strip overlaps gemm2
        dim3 gg1(16, 55), gg2(16, 9);
        gemm_kernel<<<gg1, 256, SMEM_BYTES>>>(out, 0);
        cudaEventRecord(e1, 0);
        gemm_kernel<<<gg2, 256, SMEM_BYTES>>>(out, 55);
        cudaStreamWaitEvent(s_aux, e1, 0);
        softmax_kernel<<<7040, 256, 0, s_aux>>>(out, 0);
        cudaEventRecord(e2, s_aux);
        softmax_kernel<<<1152, 256>>>(out, 7040);
        cudaStreamWaitEvent(0, e2, 0);
    } else {
        dim3 gg(16, 64);
        gemm_kernel<<<gg, 256, SMEM_BYTES>>>(out, 0);
        softmax_kernel<<<8192, 256>>>(out, 0);
    }
}